// round 7
// baseline (speedup 1.0000x reference)
#include <cuda_runtime.h>
#include <cuda_bf16.h>
#include <cstdint>

// Problem dims
#define BB    2048
#define TT    200
#define INF   1024
#define H1    2048
#define H2    1024
#define EMBED 1025   // H2 + 1 bias column

// Scratch (device globals; no allocation allowed)
__device__ float g_h1[(size_t)BB * H1];      // 16 MB
__device__ float g_h2[(size_t)BB * H2];      // 8 MB
__device__ float g_scratch[(size_t)BB * TT]; // probs scratch for loss-only layout
__device__ float g_partials[BB];

// ---------------------------------------------------------------------------
// Split-bf16 tensor-core GEMM (ROUND-4 EXACT, known-good 1e-6 numerics):
// fp32 in/out; a = ah + al (bf16 hi + residual), C ≈ ah*bh + ah*bl + al*bh,
// fp32 accumulate. CTA tile 128x128x32, 256 threads = 8 warps (2x4),
// warp tile 64x32, mma.sync.aligned.m16n8k16.row.col.f32.bf16.bf16.f32.
// ---------------------------------------------------------------------------
#define SA 40    // A smem row stride (bf16 units)
#define SB 136   // B smem row stride (bf16 units)

__device__ __forceinline__ void bf16_split(float v, unsigned short& h, unsigned short& l)
{
    __nv_bfloat16 bh = __float2bfloat16(v);
    float r = v - __bfloat162float(bh);
    __nv_bfloat16 bl = __float2bfloat16(r);
    h = reinterpret_cast<unsigned short&>(bh);
    l = reinterpret_cast<unsigned short&>(bl);
}

__device__ __forceinline__ void mma16816(float* c, const unsigned* a, unsigned b0, unsigned b1)
{
    asm volatile(
        "mma.sync.aligned.m16n8k16.row.col.f32.bf16.bf16.f32 "
        "{%0,%1,%2,%3},{%4,%5,%6,%7},{%8,%9},{%0,%1,%2,%3};\n"
        : "+f"(c[0]), "+f"(c[1]), "+f"(c[2]), "+f"(c[3])
        : "r"(a[0]), "r"(a[1]), "r"(a[2]), "r"(a[3]), "r"(b0), "r"(b1));
}

__device__ __forceinline__
void gemm_tc_body(const float* __restrict__ A, const float* __restrict__ B,
                  const float* __restrict__ bias, float* __restrict__ C,
                  int N, int K)
{
    __shared__ unsigned short Ash[128 * SA];
    __shared__ unsigned short Asl[128 * SA];
    __shared__ unsigned short Bsh[32 * SB];
    __shared__ unsigned short Bsl[32 * SB];

    const int tid  = threadIdx.x;
    const int lane = tid & 31;
    const int warp = tid >> 5;
    const int wm   = warp >> 2;      // 0..1
    const int wn   = warp & 3;       // 0..3
    const int grp  = lane >> 2;      // 0..7
    const int tg   = lane & 3;       // 0..3

    const int col0 = blockIdx.x * 128;
    const int row0 = blockIdx.y * 128;

    // loader index precompute (4 float4 per thread per operand)
    int aRow[4], aK[4], bK[4], bN[4];
#pragma unroll
    for (int i = 0; i < 4; i++) {
        int idx = tid + i * 256;
        aRow[i] = idx >> 3;        aK[i] = (idx & 7) * 4;    // A: 128 x 32
        bK[i]   = idx >> 5;        bN[i] = (idx & 31) * 4;   // B: 32 x 128
    }

    float acc[4][4][4];
#pragma unroll
    for (int mt = 0; mt < 4; mt++)
#pragma unroll
        for (int nt = 0; nt < 4; nt++)
#pragma unroll
            for (int q = 0; q < 4; q++) acc[mt][nt][q] = 0.f;

    float4 pa[4], pb[4];
    // prefetch k-tile 0
#pragma unroll
    for (int i = 0; i < 4; i++) {
        pa[i] = *(const float4*)(A + (size_t)(row0 + aRow[i]) * K + aK[i]);
        pb[i] = *(const float4*)(B + (size_t)bK[i] * N + col0 + bN[i]);
    }

    const int NITER = K / 32;
    for (int it = 0; it < NITER; ++it) {
        // convert + store current k-tile to SMEM
#pragma unroll
        for (int i = 0; i < 4; i++) {
            unsigned short h0, l0, h1, l1, h2, l2, h3, l3;
            bf16_split(pa[i].x, h0, l0); bf16_split(pa[i].y, h1, l1);
            bf16_split(pa[i].z, h2, l2); bf16_split(pa[i].w, h3, l3);
            int ba = aRow[i] * SA + aK[i];
            *(unsigned*)&Ash[ba]     = (unsigned)h0 | ((unsigned)h1 << 16);
            *(unsigned*)&Ash[ba + 2] = (unsigned)h2 | ((unsigned)h3 << 16);
            *(unsigned*)&Asl[ba]     = (unsigned)l0 | ((unsigned)l1 << 16);
            *(unsigned*)&Asl[ba + 2] = (unsigned)l2 | ((unsigned)l3 << 16);

            bf16_split(pb[i].x, h0, l0); bf16_split(pb[i].y, h1, l1);
            bf16_split(pb[i].z, h2, l2); bf16_split(pb[i].w, h3, l3);
            int bb = bK[i] * SB + bN[i];
            *(unsigned*)&Bsh[bb]     = (unsigned)h0 | ((unsigned)h1 << 16);
            *(unsigned*)&Bsh[bb + 2] = (unsigned)h2 | ((unsigned)h3 << 16);
            *(unsigned*)&Bsl[bb]     = (unsigned)l0 | ((unsigned)l1 << 16);
            *(unsigned*)&Bsl[bb + 2] = (unsigned)l2 | ((unsigned)l3 << 16);
        }
        __syncthreads();

        // prefetch next k-tile into registers (hides gmem latency behind MMAs)
        if (it + 1 < NITER) {
            const int k0n = (it + 1) * 32;
#pragma unroll
            for (int i = 0; i < 4; i++) {
                pa[i] = *(const float4*)(A + (size_t)(row0 + aRow[i]) * K + k0n + aK[i]);
                pb[i] = *(const float4*)(B + (size_t)(k0n + bK[i]) * N + col0 + bN[i]);
            }
        }

        // compute: 2 k-steps of 16
#pragma unroll
        for (int ks = 0; ks < 2; ks++) {
            const int k0 = ks * 16;
            unsigned ah[4][4], al[4][4];
#pragma unroll
            for (int mt = 0; mt < 4; mt++) {
                int r = (wm * 64 + mt * 16 + grp) * SA + k0 + 2 * tg;
                ah[mt][0] = *(const unsigned*)&Ash[r];
                ah[mt][1] = *(const unsigned*)&Ash[r + 8 * SA];
                ah[mt][2] = *(const unsigned*)&Ash[r + 8];
                ah[mt][3] = *(const unsigned*)&Ash[r + 8 * SA + 8];
                al[mt][0] = *(const unsigned*)&Asl[r];
                al[mt][1] = *(const unsigned*)&Asl[r + 8 * SA];
                al[mt][2] = *(const unsigned*)&Asl[r + 8];
                al[mt][3] = *(const unsigned*)&Asl[r + 8 * SA + 8];
            }
#pragma unroll
            for (int nt = 0; nt < 4; nt++) {
                const int n  = wn * 32 + nt * 8 + grp;
                const int kb = k0 + 2 * tg;
                unsigned bh0 = (unsigned)Bsh[kb * SB + n]       | ((unsigned)Bsh[(kb + 1) * SB + n] << 16);
                unsigned bh1 = (unsigned)Bsh[(kb + 8) * SB + n] | ((unsigned)Bsh[(kb + 9) * SB + n] << 16);
                unsigned bl0 = (unsigned)Bsl[kb * SB + n]       | ((unsigned)Bsl[(kb + 1) * SB + n] << 16);
                unsigned bl1 = (unsigned)Bsl[(kb + 8) * SB + n] | ((unsigned)Bsl[(kb + 9) * SB + n] << 16);
#pragma unroll
                for (int mt = 0; mt < 4; mt++) {
                    mma16816(acc[mt][nt], ah[mt], bh0, bh1);  // hi*hi
                    mma16816(acc[mt][nt], ah[mt], bl0, bl1);  // hi*lo
                    mma16816(acc[mt][nt], al[mt], bh0, bh1);  // lo*hi
                }
            }
        }
        __syncthreads();
    }

    // epilogue: bias + relu, float2 stores
#pragma unroll
    for (int mt = 0; mt < 4; mt++) {
        const int r = row0 + wm * 64 + mt * 16 + grp;
#pragma unroll
        for (int nt = 0; nt < 4; nt++) {
            const int c = col0 + wn * 32 + nt * 8 + 2 * tg;
            const float2 bv = *(const float2*)(bias + c);
            float2 o;
            o.x = fmaxf(acc[mt][nt][0] + bv.x, 0.f);
            o.y = fmaxf(acc[mt][nt][1] + bv.y, 0.f);
            *(float2*)&C[(size_t)r * N + c] = o;
            o.x = fmaxf(acc[mt][nt][2] + bv.x, 0.f);
            o.y = fmaxf(acc[mt][nt][3] + bv.y, 0.f);
            *(float2*)&C[(size_t)(r + 8) * N + c] = o;
        }
    }
}

__global__ __launch_bounds__(256, 1)
void gemm1_kernel(const float* __restrict__ x, const float* __restrict__ W1,
                  const float* __restrict__ b1)
{
    gemm_tc_body(x, W1, b1, g_h1, H1, INF);
}

__global__ __launch_bounds__(256, 1)
void gemm2_kernel(const float* __restrict__ W2, const float* __restrict__ b2)
{
    gemm_tc_body(g_h1, W2, b2, g_h2, H2, H1);
}

// ---------------------------------------------------------------------------
// Gather + dot + BCE + sigmoid. One block per batch row b.
// h2[b] held in REGISTERS (32 per lane), reused across this warp's 25 targets.
// 2 targets in flight per iteration (64 outstanding LDGs).
// emb rows only 4-byte aligned (stride 1025 floats) -> scalar LDG.32 only.
// ---------------------------------------------------------------------------
__global__ __launch_bounds__(256)
void gather_bce_kernel(const float* __restrict__ emb,
                       const int*   __restrict__ ids,
                       const float* __restrict__ tv,
                       const float* __restrict__ tm,
                       float* __restrict__ probs)
{
    __shared__ float warp_part[8];

    if (probs == nullptr) probs = g_scratch;   // loss-only layout: scratch

    const int b    = blockIdx.x;
    const int tid  = threadIdx.x;
    const int lane = tid & 31;
    const int w    = tid >> 5;

    float hreg[32];
#pragma unroll
    for (int i = 0; i < 32; i++)
        hreg[i] = g_h2[(size_t)b * H2 + lane + i * 32];

    float part = 0.f;

    auto finish = [&](float z, int t) {
        if (lane == 0) {
            const float y = tv[b * TT + t];
            const float m = tm[b * TT + t];
            const float bce = fmaxf(z, 0.f) - z * y + log1pf(expf(-fabsf(z)));
            part += m * bce;
            probs[b * TT + t] = 1.f / (1.f + expf(-z));
        }
    };

    // 25 targets per warp = 12 pairs + 1 tail
#pragma unroll 1
    for (int j = 0; j < 12; j++) {
        const int t0 = w + 16 * j;
        const int t1 = t0 + 8;
        const int id0 = ids[b * TT + t0];
        const int id1 = ids[b * TT + t1];
        const float* e0 = emb + (size_t)id0 * EMBED;
        const float* e1 = emb + (size_t)id1 * EMBED;
        float a0 = 0.f, a1 = 0.f;
        if (id0 != 0 && id1 != 0) {
#pragma unroll
            for (int i = 0; i < 32; i++) {
                a0 = fmaf(__ldg(e0 + lane + i * 32), hreg[i], a0);
                a1 = fmaf(__ldg(e1 + lane + i * 32), hreg[i], a1);
            }
        } else {
            if (id0 != 0)
#pragma unroll
                for (int i = 0; i < 32; i++) a0 = fmaf(__ldg(e0 + lane + i * 32), hreg[i], a0);
            if (id1 != 0)
#pragma unroll
                for (int i = 0; i < 32; i++) a1 = fmaf(__ldg(e1 + lane + i * 32), hreg[i], a1);
        }
#pragma unroll
        for (int o = 16; o; o >>= 1) {
            a0 += __shfl_xor_sync(0xffffffffu, a0, o);
            a1 += __shfl_xor_sync(0xffffffffu, a1, o);
        }
        float z0 = (id0 != 0) ? a0 + __ldg(e0 + 1024) : 0.f;
        float z1 = (id1 != 0) ? a1 + __ldg(e1 + 1024) : 0.f;
        finish(z0, t0);
        finish(z1, t1);
    }
    {
        const int t = w + 192;
        const int id = ids[b * TT + t];
        float z = 0.f;
        if (id != 0) {
            const float* er = emb + (size_t)id * EMBED;
            float a = 0.f;
#pragma unroll
            for (int i = 0; i < 32; i++)
                a = fmaf(__ldg(er + lane + i * 32), hreg[i], a);
#pragma unroll
            for (int o = 16; o; o >>= 1)
                a += __shfl_xor_sync(0xffffffffu, a, o);
            z = a + __ldg(er + 1024);
        }
        finish(z, t);
    }

    if (lane == 0) warp_part[w] = part;
    __syncthreads();
    if (tid == 0) {
        float s = 0.f;
#pragma unroll
        for (int i = 0; i < 8; i++) s += warp_part[i];
        g_partials[b] = s;
    }
}

// Deterministic final reduction.
__global__ __launch_bounds__(256)
void finalize_loss(float* __restrict__ out)
{
    __shared__ float s[256];
    float acc = 0.f;
    for (int i = threadIdx.x; i < BB; i += 256) acc += g_partials[i];
    s[threadIdx.x] = acc;
    __syncthreads();
    for (int o = 128; o; o >>= 1) {
        if (threadIdx.x < o) s[threadIdx.x] += s[threadIdx.x + o];
        __syncthreads();
    }
    if (threadIdx.x == 0) out[0] = s[0] / (float)((size_t)BB * TT);
}

// ---------------------------------------------------------------------------
extern "C" void kernel_launch(void* const* d_in, const int* in_sizes, int n_in,
                              void* d_out, int out_size)
{
    const float* x   = (const float*)d_in[0];
    const float* W1  = (const float*)d_in[1];
    const float* b1  = (const float*)d_in[2];
    const float* W2  = (const float*)d_in[3];
    const float* b2  = (const float*)d_in[4];
    const float* emb = (const float*)d_in[5];
    const int*   ids = (const int*)  d_in[6];
    const float* tv  = (const float*)d_in[7];
    const float* tm  = (const float*)d_in[8];
    float* out = (float*)d_out;

    // GEMM1: [2048,1024] @ [1024,2048] -> g_h1
    {
        dim3 grid(H1 / 128, BB / 128);
        gemm1_kernel<<<grid, 256>>>(x, W1, b1);
    }
    // GEMM2: [2048,2048] @ [2048,1024] -> g_h2
    {
        dim3 grid(H2 / 128, BB / 128);
        gemm2_kernel<<<grid, 256>>>(W2, b2);
    }

    const int nBT = BB * TT;
    float* probs    = nullptr;   // nullptr -> scratch inside kernel
    float* loss_dst = nullptr;
    if (out_size >= nBT + 1)      { loss_dst = out; probs = out + 1; }
    else if (out_size == nBT)     { probs = out; }
    else                          { loss_dst = out; }

    gather_bce_kernel<<<BB, 256>>>(emb, ids, tv, tm, probs);

    if (loss_dst != nullptr) {
        finalize_loss<<<1, 256>>>(loss_dst);
    }
}

// round 8
// speedup vs baseline: 1.1181x; 1.1181x over previous
#include <cuda_runtime.h>
#include <cuda_bf16.h>
#include <cstdint>

// Problem dims
#define BB    2048
#define TT    200
#define INF   1024
#define H1    2048
#define H2    1024
#define EMBED 1025   // H2 + 1 bias column

#define GSPLIT 4                 // CTAs per batch row in gather
#define TPC    (TT / GSPLIT)     // 50 targets per CTA

// Scratch (device globals; no allocation allowed)
__device__ float g_h1[(size_t)BB * H1];        // 16 MB
__device__ float g_h2[(size_t)BB * H2];        // 8 MB
__device__ float g_scratch[(size_t)BB * TT];   // probs scratch for loss-only layout
__device__ float g_partials[BB * GSPLIT];      // per-CTA partial sums

// ---------------------------------------------------------------------------
// Split-bf16 tensor-core GEMM (ROUND-4 EXACT, known-good):
// fp32 in/out; a = ah + al (bf16 hi + residual), C ≈ ah*bh + ah*bl + al*bh,
// fp32 accumulate. CTA tile 128x128x32, 256 threads = 8 warps (2x4),
// warp tile 64x32, mma.sync.aligned.m16n8k16.row.col.f32.bf16.bf16.f32.
// ---------------------------------------------------------------------------
#define SA 40    // A smem row stride (bf16 units)
#define SB 136   // B smem row stride (bf16 units)

__device__ __forceinline__ void bf16_split(float v, unsigned short& h, unsigned short& l)
{
    __nv_bfloat16 bh = __float2bfloat16(v);
    float r = v - __bfloat162float(bh);
    __nv_bfloat16 bl = __float2bfloat16(r);
    h = reinterpret_cast<unsigned short&>(bh);
    l = reinterpret_cast<unsigned short&>(bl);
}

__device__ __forceinline__ void mma16816(float* c, const unsigned* a, unsigned b0, unsigned b1)
{
    asm volatile(
        "mma.sync.aligned.m16n8k16.row.col.f32.bf16.bf16.f32 "
        "{%0,%1,%2,%3},{%4,%5,%6,%7},{%8,%9},{%0,%1,%2,%3};\n"
        : "+f"(c[0]), "+f"(c[1]), "+f"(c[2]), "+f"(c[3])
        : "r"(a[0]), "r"(a[1]), "r"(a[2]), "r"(a[3]), "r"(b0), "r"(b1));
}

__device__ __forceinline__
void gemm_tc_body(const float* __restrict__ A, const float* __restrict__ B,
                  const float* __restrict__ bias, float* __restrict__ C,
                  int N, int K)
{
    __shared__ unsigned short Ash[128 * SA];
    __shared__ unsigned short Asl[128 * SA];
    __shared__ unsigned short Bsh[32 * SB];
    __shared__ unsigned short Bsl[32 * SB];

    const int tid  = threadIdx.x;
    const int lane = tid & 31;
    const int warp = tid >> 5;
    const int wm   = warp >> 2;      // 0..1
    const int wn   = warp & 3;       // 0..3
    const int grp  = lane >> 2;      // 0..7
    const int tg   = lane & 3;       // 0..3

    const int col0 = blockIdx.x * 128;
    const int row0 = blockIdx.y * 128;

    int aRow[4], aK[4], bK[4], bN[4];
#pragma unroll
    for (int i = 0; i < 4; i++) {
        int idx = tid + i * 256;
        aRow[i] = idx >> 3;        aK[i] = (idx & 7) * 4;    // A: 128 x 32
        bK[i]   = idx >> 5;        bN[i] = (idx & 31) * 4;   // B: 32 x 128
    }

    float acc[4][4][4];
#pragma unroll
    for (int mt = 0; mt < 4; mt++)
#pragma unroll
        for (int nt = 0; nt < 4; nt++)
#pragma unroll
            for (int q = 0; q < 4; q++) acc[mt][nt][q] = 0.f;

    float4 pa[4], pb[4];
#pragma unroll
    for (int i = 0; i < 4; i++) {
        pa[i] = *(const float4*)(A + (size_t)(row0 + aRow[i]) * K + aK[i]);
        pb[i] = *(const float4*)(B + (size_t)bK[i] * N + col0 + bN[i]);
    }

    const int NITER = K / 32;
    for (int it = 0; it < NITER; ++it) {
#pragma unroll
        for (int i = 0; i < 4; i++) {
            unsigned short h0, l0, h1, l1, h2, l2, h3, l3;
            bf16_split(pa[i].x, h0, l0); bf16_split(pa[i].y, h1, l1);
            bf16_split(pa[i].z, h2, l2); bf16_split(pa[i].w, h3, l3);
            int ba = aRow[i] * SA + aK[i];
            *(unsigned*)&Ash[ba]     = (unsigned)h0 | ((unsigned)h1 << 16);
            *(unsigned*)&Ash[ba + 2] = (unsigned)h2 | ((unsigned)h3 << 16);
            *(unsigned*)&Asl[ba]     = (unsigned)l0 | ((unsigned)l1 << 16);
            *(unsigned*)&Asl[ba + 2] = (unsigned)l2 | ((unsigned)l3 << 16);

            bf16_split(pb[i].x, h0, l0); bf16_split(pb[i].y, h1, l1);
            bf16_split(pb[i].z, h2, l2); bf16_split(pb[i].w, h3, l3);
            int bb = bK[i] * SB + bN[i];
            *(unsigned*)&Bsh[bb]     = (unsigned)h0 | ((unsigned)h1 << 16);
            *(unsigned*)&Bsh[bb + 2] = (unsigned)h2 | ((unsigned)h3 << 16);
            *(unsigned*)&Bsl[bb]     = (unsigned)l0 | ((unsigned)l1 << 16);
            *(unsigned*)&Bsl[bb + 2] = (unsigned)l2 | ((unsigned)l3 << 16);
        }
        __syncthreads();

        if (it + 1 < NITER) {
            const int k0n = (it + 1) * 32;
#pragma unroll
            for (int i = 0; i < 4; i++) {
                pa[i] = *(const float4*)(A + (size_t)(row0 + aRow[i]) * K + k0n + aK[i]);
                pb[i] = *(const float4*)(B + (size_t)(k0n + bK[i]) * N + col0 + bN[i]);
            }
        }

#pragma unroll
        for (int ks = 0; ks < 2; ks++) {
            const int k0 = ks * 16;
            unsigned ah[4][4], al[4][4];
#pragma unroll
            for (int mt = 0; mt < 4; mt++) {
                int r = (wm * 64 + mt * 16 + grp) * SA + k0 + 2 * tg;
                ah[mt][0] = *(const unsigned*)&Ash[r];
                ah[mt][1] = *(const unsigned*)&Ash[r + 8 * SA];
                ah[mt][2] = *(const unsigned*)&Ash[r + 8];
                ah[mt][3] = *(const unsigned*)&Ash[r + 8 * SA + 8];
                al[mt][0] = *(const unsigned*)&Asl[r];
                al[mt][1] = *(const unsigned*)&Asl[r + 8 * SA];
                al[mt][2] = *(const unsigned*)&Asl[r + 8];
                al[mt][3] = *(const unsigned*)&Asl[r + 8 * SA + 8];
            }
#pragma unroll
            for (int nt = 0; nt < 4; nt++) {
                const int n  = wn * 32 + nt * 8 + grp;
                const int kb = k0 + 2 * tg;
                unsigned bh0 = (unsigned)Bsh[kb * SB + n]       | ((unsigned)Bsh[(kb + 1) * SB + n] << 16);
                unsigned bh1 = (unsigned)Bsh[(kb + 8) * SB + n] | ((unsigned)Bsh[(kb + 9) * SB + n] << 16);
                unsigned bl0 = (unsigned)Bsl[kb * SB + n]       | ((unsigned)Bsl[(kb + 1) * SB + n] << 16);
                unsigned bl1 = (unsigned)Bsl[(kb + 8) * SB + n] | ((unsigned)Bsl[(kb + 9) * SB + n] << 16);
#pragma unroll
                for (int mt = 0; mt < 4; mt++) {
                    mma16816(acc[mt][nt], ah[mt], bh0, bh1);  // hi*hi
                    mma16816(acc[mt][nt], ah[mt], bl0, bl1);  // hi*lo
                    mma16816(acc[mt][nt], al[mt], bh0, bh1);  // lo*hi
                }
            }
        }
        __syncthreads();
    }

#pragma unroll
    for (int mt = 0; mt < 4; mt++) {
        const int r = row0 + wm * 64 + mt * 16 + grp;
#pragma unroll
        for (int nt = 0; nt < 4; nt++) {
            const int c = col0 + wn * 32 + nt * 8 + 2 * tg;
            const float2 bv = *(const float2*)(bias + c);
            float2 o;
            o.x = fmaxf(acc[mt][nt][0] + bv.x, 0.f);
            o.y = fmaxf(acc[mt][nt][1] + bv.y, 0.f);
            *(float2*)&C[(size_t)r * N + c] = o;
            o.x = fmaxf(acc[mt][nt][2] + bv.x, 0.f);
            o.y = fmaxf(acc[mt][nt][3] + bv.y, 0.f);
            *(float2*)&C[(size_t)(r + 8) * N + c] = o;
        }
    }
}

__global__ __launch_bounds__(256, 1)
void gemm1_kernel(const float* __restrict__ x, const float* __restrict__ W1,
                  const float* __restrict__ b1)
{
    gemm_tc_body(x, W1, b1, g_h1, H1, INF);
}

__global__ __launch_bounds__(256, 1)
void gemm2_kernel(const float* __restrict__ W2, const float* __restrict__ b2)
{
    gemm_tc_body(g_h1, W2, b2, g_h2, H2, H1);
}

// ---------------------------------------------------------------------------
// Gather + dot + BCE + sigmoid. GSPLIT CTAs per batch row (grid = BB*GSPLIT);
// each CTA stages h2[b] in SMEM and handles TPC=50 targets.
// Round-4 per-target inner loop (low regs, SMEM h) — proven fastest form;
// the extra CTAs supply memory-level parallelism instead of registers.
// emb rows only 4-byte aligned (stride 1025 floats) -> scalar LDG.32 only.
// ---------------------------------------------------------------------------
__global__ __launch_bounds__(256)
void gather_bce_kernel(const float* __restrict__ emb,
                       const int*   __restrict__ ids,
                       const float* __restrict__ tv,
                       const float* __restrict__ tm,
                       float* __restrict__ probs)
{
    __shared__ float hs[H2];
    __shared__ float warp_part[8];

    if (probs == nullptr) probs = g_scratch;   // loss-only layout: scratch

    const int blk   = blockIdx.x;
    const int b     = blk >> 2;        // batch row       (GSPLIT == 4)
    const int chunk = blk & 3;         // target chunk
    const int tid   = threadIdx.x;
    const int lane  = tid & 31;
    const int w     = tid >> 5;

    // stage h2 row: 256 threads x float4 = 1024 floats
    ((float4*)hs)[tid] = ((const float4*)(g_h2 + (size_t)b * H2))[tid];
    __syncthreads();

    const int tbase = chunk * TPC;
    float part = 0.f;
    for (int tl = w; tl < TPC; tl += 8) {
        const int t  = tbase + tl;
        const int id = ids[b * TT + t];
        float z = 0.f;
        if (id != 0) {
            const float* er = emb + (size_t)id * EMBED;
            float acc = 0.f;
#pragma unroll
            for (int i = 0; i < 32; i++)
                acc = fmaf(__ldg(er + lane + i * 32), hs[lane + i * 32], acc);
#pragma unroll
            for (int o = 16; o; o >>= 1)
                acc += __shfl_xor_sync(0xffffffffu, acc, o);
            z = acc + __ldg(er + 1024);
        }
        if (lane == 0) {
            const float y = tv[b * TT + t];
            const float m = tm[b * TT + t];
            const float bce = fmaxf(z, 0.f) - z * y + log1pf(expf(-fabsf(z)));
            part += m * bce;
            probs[b * TT + t] = 1.f / (1.f + expf(-z));
        }
    }
    if (lane == 0) warp_part[w] = part;
    __syncthreads();
    if (tid == 0) {
        float s = 0.f;
#pragma unroll
        for (int i = 0; i < 8; i++) s += warp_part[i];
        g_partials[blk] = s;
    }
}

// Deterministic final reduction: fixed-order tree over BB*GSPLIT partials.
__global__ __launch_bounds__(256)
void finalize_loss(float* __restrict__ out)
{
    __shared__ float s[256];
    float acc = 0.f;
    for (int i = threadIdx.x; i < BB * GSPLIT; i += 256) acc += g_partials[i];
    s[threadIdx.x] = acc;
    __syncthreads();
    for (int o = 128; o; o >>= 1) {
        if (threadIdx.x < o) s[threadIdx.x] += s[threadIdx.x + o];
        __syncthreads();
    }
    if (threadIdx.x == 0) out[0] = s[0] / (float)((size_t)BB * TT);
}

// ---------------------------------------------------------------------------
extern "C" void kernel_launch(void* const* d_in, const int* in_sizes, int n_in,
                              void* d_out, int out_size)
{
    const float* x   = (const float*)d_in[0];
    const float* W1  = (const float*)d_in[1];
    const float* b1  = (const float*)d_in[2];
    const float* W2  = (const float*)d_in[3];
    const float* b2  = (const float*)d_in[4];
    const float* emb = (const float*)d_in[5];
    const int*   ids = (const int*)  d_in[6];
    const float* tv  = (const float*)d_in[7];
    const float* tm  = (const float*)d_in[8];
    float* out = (float*)d_out;

    // GEMM1: [2048,1024] @ [1024,2048] -> g_h1
    {
        dim3 grid(H1 / 128, BB / 128);
        gemm1_kernel<<<grid, 256>>>(x, W1, b1);
    }
    // GEMM2: [2048,2048] @ [2048,1024] -> g_h2
    {
        dim3 grid(H2 / 128, BB / 128);
        gemm2_kernel<<<grid, 256>>>(W2, b2);
    }

    const int nBT = BB * TT;
    float* probs    = nullptr;   // nullptr -> scratch inside kernel
    float* loss_dst = nullptr;
    if (out_size >= nBT + 1)      { loss_dst = out; probs = out + 1; }
    else if (out_size == nBT)     { probs = out; }
    else                          { loss_dst = out; }

    gather_bce_kernel<<<BB * GSPLIT, 256>>>(emb, ids, tv, tm, probs);

    if (loss_dst != nullptr) {
        finalize_loss<<<1, 256>>>(loss_dst);
    }
}

// round 9
// speedup vs baseline: 1.1325x; 1.0129x over previous
#include <cuda_runtime.h>
#include <cuda_bf16.h>
#include <cstdint>

// Problem dims
#define BB    2048
#define TT    200
#define INF   1024
#define H1    2048
#define H2    1024
#define EMBED 1025   // H2 + 1 bias column

#define GSPLIT 4                 // CTAs per batch row in gather
#define TPC    (TT / GSPLIT)     // 50 targets per CTA

// Scratch (device globals; no allocation allowed)
__device__ float g_h1[(size_t)BB * H1];        // 16 MB
__device__ float g_h2[(size_t)BB * H2];        // 8 MB
__device__ float g_scratch[(size_t)BB * TT];   // probs scratch for loss-only layout
__device__ float g_partials[BB * GSPLIT];      // per-CTA partial sums

// ---------------------------------------------------------------------------
// Split-bf16 tensor-core GEMM, 2-STAGE double-buffered SMEM (1 sync/iter).
// Numerics identical to round-4 body: a = ah + al, C ≈ ah*bh + ah*bl + al*bh,
// fp32 accumulate. CTA tile 128x128x32, 256 threads = 8 warps (2x4),
// warp tile 64x32, mma.sync.aligned.m16n8k16.row.col.f32.bf16.bf16.f32.
// ---------------------------------------------------------------------------
#define SA 40    // A smem row stride (bf16 units)
#define SB 136   // B smem row stride (bf16 units)
#define A_SZ (128 * SA)              // 5120 ushorts
#define B_SZ (32 * SB)               // 4352 ushorts
#define STAGE_SZ (2 * A_SZ + 2 * B_SZ)   // 18944 ushorts per stage
#define GEMM_SMEM_BYTES (2 * STAGE_SZ * 2)  // 75776 bytes

__device__ __forceinline__ void bf16_split(float v, unsigned short& h, unsigned short& l)
{
    __nv_bfloat16 bh = __float2bfloat16(v);
    float r = v - __bfloat162float(bh);
    __nv_bfloat16 bl = __float2bfloat16(r);
    h = reinterpret_cast<unsigned short&>(bh);
    l = reinterpret_cast<unsigned short&>(bl);
}

__device__ __forceinline__ void mma16816(float* c, const unsigned* a, unsigned b0, unsigned b1)
{
    asm volatile(
        "mma.sync.aligned.m16n8k16.row.col.f32.bf16.bf16.f32 "
        "{%0,%1,%2,%3},{%4,%5,%6,%7},{%8,%9},{%0,%1,%2,%3};\n"
        : "+f"(c[0]), "+f"(c[1]), "+f"(c[2]), "+f"(c[3])
        : "r"(a[0]), "r"(a[1]), "r"(a[2]), "r"(a[3]), "r"(b0), "r"(b1));
}

__device__ __forceinline__
void gemm_tc_body(const float* __restrict__ A, const float* __restrict__ B,
                  const float* __restrict__ bias, float* __restrict__ C,
                  int N, int K)
{
    extern __shared__ unsigned short dsm[];

    const int tid  = threadIdx.x;
    const int lane = tid & 31;
    const int warp = tid >> 5;
    const int wm   = warp >> 2;      // 0..1
    const int wn   = warp & 3;       // 0..3
    const int grp  = lane >> 2;      // 0..7
    const int tg   = lane & 3;       // 0..3

    const int col0 = blockIdx.x * 128;
    const int row0 = blockIdx.y * 128;

    int aRow[4], aK[4], bK[4], bN[4];
#pragma unroll
    for (int i = 0; i < 4; i++) {
        int idx = tid + i * 256;
        aRow[i] = idx >> 3;        aK[i] = (idx & 7) * 4;    // A: 128 x 32
        bK[i]   = idx >> 5;        bN[i] = (idx & 31) * 4;   // B: 32 x 128
    }

    float acc[4][4][4];
#pragma unroll
    for (int mt = 0; mt < 4; mt++)
#pragma unroll
        for (int nt = 0; nt < 4; nt++)
#pragma unroll
            for (int q = 0; q < 4; q++) acc[mt][nt][q] = 0.f;

    float4 pa[4], pb[4];

    auto load_tile = [&](int k0) {
#pragma unroll
        for (int i = 0; i < 4; i++) {
            pa[i] = *(const float4*)(A + (size_t)(row0 + aRow[i]) * K + k0 + aK[i]);
            pb[i] = *(const float4*)(B + (size_t)(k0 + bK[i]) * N + col0 + bN[i]);
        }
    };

    auto store_tile = [&](int st) {
        unsigned short* Ash = dsm + st * STAGE_SZ;
        unsigned short* Asl = Ash + A_SZ;
        unsigned short* Bsh = Asl + A_SZ;
        unsigned short* Bsl = Bsh + B_SZ;
#pragma unroll
        for (int i = 0; i < 4; i++) {
            unsigned short h0, l0, h1, l1, h2, l2, h3, l3;
            bf16_split(pa[i].x, h0, l0); bf16_split(pa[i].y, h1, l1);
            bf16_split(pa[i].z, h2, l2); bf16_split(pa[i].w, h3, l3);
            int ba = aRow[i] * SA + aK[i];
            *(unsigned*)&Ash[ba]     = (unsigned)h0 | ((unsigned)h1 << 16);
            *(unsigned*)&Ash[ba + 2] = (unsigned)h2 | ((unsigned)h3 << 16);
            *(unsigned*)&Asl[ba]     = (unsigned)l0 | ((unsigned)l1 << 16);
            *(unsigned*)&Asl[ba + 2] = (unsigned)l2 | ((unsigned)l3 << 16);

            bf16_split(pb[i].x, h0, l0); bf16_split(pb[i].y, h1, l1);
            bf16_split(pb[i].z, h2, l2); bf16_split(pb[i].w, h3, l3);
            int bb = bK[i] * SB + bN[i];
            *(unsigned*)&Bsh[bb]     = (unsigned)h0 | ((unsigned)h1 << 16);
            *(unsigned*)&Bsh[bb + 2] = (unsigned)h2 | ((unsigned)h3 << 16);
            *(unsigned*)&Bsl[bb]     = (unsigned)l0 | ((unsigned)l1 << 16);
            *(unsigned*)&Bsl[bb + 2] = (unsigned)l2 | ((unsigned)l3 << 16);
        }
    };

    auto compute_stage = [&](int st) {
        unsigned short* Ash = dsm + st * STAGE_SZ;
        unsigned short* Asl = Ash + A_SZ;
        unsigned short* Bsh = Asl + A_SZ;
        unsigned short* Bsl = Bsh + B_SZ;
#pragma unroll
        for (int ks = 0; ks < 2; ks++) {
            const int k0 = ks * 16;
            unsigned ah[4][4], al[4][4];
#pragma unroll
            for (int mt = 0; mt < 4; mt++) {
                int r = (wm * 64 + mt * 16 + grp) * SA + k0 + 2 * tg;
                ah[mt][0] = *(const unsigned*)&Ash[r];
                ah[mt][1] = *(const unsigned*)&Ash[r + 8 * SA];
                ah[mt][2] = *(const unsigned*)&Ash[r + 8];
                ah[mt][3] = *(const unsigned*)&Ash[r + 8 * SA + 8];
                al[mt][0] = *(const unsigned*)&Asl[r];
                al[mt][1] = *(const unsigned*)&Asl[r + 8 * SA];
                al[mt][2] = *(const unsigned*)&Asl[r + 8];
                al[mt][3] = *(const unsigned*)&Asl[r + 8 * SA + 8];
            }
#pragma unroll
            for (int nt = 0; nt < 4; nt++) {
                const int n  = wn * 32 + nt * 8 + grp;
                const int kb = k0 + 2 * tg;
                unsigned bh0 = (unsigned)Bsh[kb * SB + n]       | ((unsigned)Bsh[(kb + 1) * SB + n] << 16);
                unsigned bh1 = (unsigned)Bsh[(kb + 8) * SB + n] | ((unsigned)Bsh[(kb + 9) * SB + n] << 16);
                unsigned bl0 = (unsigned)Bsl[kb * SB + n]       | ((unsigned)Bsl[(kb + 1) * SB + n] << 16);
                unsigned bl1 = (unsigned)Bsl[(kb + 8) * SB + n] | ((unsigned)Bsl[(kb + 9) * SB + n] << 16);
#pragma unroll
                for (int mt = 0; mt < 4; mt++) {
                    mma16816(acc[mt][nt], ah[mt], bh0, bh1);  // hi*hi
                    mma16816(acc[mt][nt], ah[mt], bl0, bl1);  // hi*lo
                    mma16816(acc[mt][nt], al[mt], bh0, bh1);  // lo*hi
                }
            }
        }
    };

    const int NITER = K / 32;

    // prologue: tile 0 -> stage 0
    load_tile(0);
    store_tile(0);
    __syncthreads();

    for (int it = 0; it < NITER; ++it) {
        const int cur = it & 1;
        const bool more = (it + 1 < NITER);
        if (more) load_tile((it + 1) * 32);     // gmem loads in flight during compute
        compute_stage(cur);
        if (more) {
            store_tile(cur ^ 1);                // write other stage; no one reads it now
            __syncthreads();                    // single barrier per iteration
        }
    }

    // epilogue: bias + relu, float2 stores
#pragma unroll
    for (int mt = 0; mt < 4; mt++) {
        const int r = row0 + wm * 64 + mt * 16 + grp;
#pragma unroll
        for (int nt = 0; nt < 4; nt++) {
            const int c = col0 + wn * 32 + nt * 8 + 2 * tg;
            const float2 bv = *(const float2*)(bias + c);
            float2 o;
            o.x = fmaxf(acc[mt][nt][0] + bv.x, 0.f);
            o.y = fmaxf(acc[mt][nt][1] + bv.y, 0.f);
            *(float2*)&C[(size_t)r * N + c] = o;
            o.x = fmaxf(acc[mt][nt][2] + bv.x, 0.f);
            o.y = fmaxf(acc[mt][nt][3] + bv.y, 0.f);
            *(float2*)&C[(size_t)(r + 8) * N + c] = o;
        }
    }
}

__global__ __launch_bounds__(256, 1)
void gemm1_kernel(const float* __restrict__ x, const float* __restrict__ W1,
                  const float* __restrict__ b1)
{
    gemm_tc_body(x, W1, b1, g_h1, H1, INF);
}

__global__ __launch_bounds__(256, 1)
void gemm2_kernel(const float* __restrict__ W2, const float* __restrict__ b2)
{
    gemm_tc_body(g_h1, W2, b2, g_h2, H2, H1);
}

// ---------------------------------------------------------------------------
// Gather + dot + BCE + sigmoid (round-8 exact: GSPLIT CTAs per batch row,
// SMEM-staged h, low registers).
// emb rows only 4-byte aligned (stride 1025 floats) -> scalar LDG.32 only.
// ---------------------------------------------------------------------------
__global__ __launch_bounds__(256)
void gather_bce_kernel(const float* __restrict__ emb,
                       const int*   __restrict__ ids,
                       const float* __restrict__ tv,
                       const float* __restrict__ tm,
                       float* __restrict__ probs)
{
    __shared__ float hs[H2];
    __shared__ float warp_part[8];

    if (probs == nullptr) probs = g_scratch;   // loss-only layout: scratch

    const int blk   = blockIdx.x;
    const int b     = blk >> 2;        // batch row       (GSPLIT == 4)
    const int chunk = blk & 3;         // target chunk
    const int tid   = threadIdx.x;
    const int lane  = tid & 31;
    const int w     = tid >> 5;

    ((float4*)hs)[tid] = ((const float4*)(g_h2 + (size_t)b * H2))[tid];
    __syncthreads();

    const int tbase = chunk * TPC;
    float part = 0.f;
    for (int tl = w; tl < TPC; tl += 8) {
        const int t  = tbase + tl;
        const int id = ids[b * TT + t];
        float z = 0.f;
        if (id != 0) {
            const float* er = emb + (size_t)id * EMBED;
            float acc = 0.f;
#pragma unroll
            for (int i = 0; i < 32; i++)
                acc = fmaf(__ldg(er + lane + i * 32), hs[lane + i * 32], acc);
#pragma unroll
            for (int o = 16; o; o >>= 1)
                acc += __shfl_xor_sync(0xffffffffu, acc, o);
            z = acc + __ldg(er + 1024);
        }
        if (lane == 0) {
            const float y = tv[b * TT + t];
            const float m = tm[b * TT + t];
            const float bce = fmaxf(z, 0.f) - z * y + log1pf(expf(-fabsf(z)));
            part += m * bce;
            probs[b * TT + t] = 1.f / (1.f + expf(-z));
        }
    }
    if (lane == 0) warp_part[w] = part;
    __syncthreads();
    if (tid == 0) {
        float s = 0.f;
#pragma unroll
        for (int i = 0; i < 8; i++) s += warp_part[i];
        g_partials[blk] = s;
    }
}

// Deterministic final reduction: fixed-order tree over BB*GSPLIT partials.
__global__ __launch_bounds__(256)
void finalize_loss(float* __restrict__ out)
{
    __shared__ float s[256];
    float acc = 0.f;
    for (int i = threadIdx.x; i < BB * GSPLIT; i += 256) acc += g_partials[i];
    s[threadIdx.x] = acc;
    __syncthreads();
    for (int o = 128; o; o >>= 1) {
        if (threadIdx.x < o) s[threadIdx.x] += s[threadIdx.x + o];
        __syncthreads();
    }
    if (threadIdx.x == 0) out[0] = s[0] / (float)((size_t)BB * TT);
}

// ---------------------------------------------------------------------------
extern "C" void kernel_launch(void* const* d_in, const int* in_sizes, int n_in,
                              void* d_out, int out_size)
{
    const float* x   = (const float*)d_in[0];
    const float* W1  = (const float*)d_in[1];
    const float* b1  = (const float*)d_in[2];
    const float* W2  = (const float*)d_in[3];
    const float* b2  = (const float*)d_in[4];
    const float* emb = (const float*)d_in[5];
    const int*   ids = (const int*)  d_in[6];
    const float* tv  = (const float*)d_in[7];
    const float* tm  = (const float*)d_in[8];
    float* out = (float*)d_out;

    // Opt in to >48KB dynamic smem (idempotent; not a stream op -> capture-safe)
    cudaFuncSetAttribute(gemm1_kernel, cudaFuncAttributeMaxDynamicSharedMemorySize, GEMM_SMEM_BYTES);
    cudaFuncSetAttribute(gemm2_kernel, cudaFuncAttributeMaxDynamicSharedMemorySize, GEMM_SMEM_BYTES);

    // GEMM1: [2048,1024] @ [1024,2048] -> g_h1
    {
        dim3 grid(H1 / 128, BB / 128);
        gemm1_kernel<<<grid, 256, GEMM_SMEM_BYTES>>>(x, W1, b1);
    }
    // GEMM2: [2048,2048] @ [2048,1024] -> g_h2
    {
        dim3 grid(H2 / 128, BB / 128);
        gemm2_kernel<<<grid, 256, GEMM_SMEM_BYTES>>>(W2, b2);
    }

    const int nBT = BB * TT;
    float* probs    = nullptr;   // nullptr -> scratch inside kernel
    float* loss_dst = nullptr;
    if (out_size >= nBT + 1)      { loss_dst = out; probs = out + 1; }
    else if (out_size == nBT)     { probs = out; }
    else                          { loss_dst = out; }

    gather_bce_kernel<<<BB * GSPLIT, 256>>>(emb, ids, tv, tm, probs);

    if (loss_dst != nullptr) {
        finalize_loss<<<1, 256>>>(loss_dst);
    }
}

// round 11
// speedup vs baseline: 1.1367x; 1.0037x over previous
#include <cuda_runtime.h>
#include <cuda_bf16.h>
#include <cstdint>

// Problem dims
#define BB    2048
#define TT    200
#define INF   1024
#define H1    2048
#define H2    1024
#define EMBED 1025   // H2 + 1 bias column

#define GSPLIT 4                 // CTAs per batch row in gather
#define TPC    (TT / GSPLIT)     // 50 targets per CTA

// Scratch (device globals; no allocation allowed)
__device__ float g_h1[(size_t)BB * H1];        // 16 MB
__device__ float g_h2[(size_t)BB * H2];        // 8 MB
__device__ float g_scratch[(size_t)BB * TT];   // probs scratch for loss-only layout
__device__ float g_partials[BB * GSPLIT];      // per-CTA partial sums

// ---------------------------------------------------------------------------
// Split-bf16 tensor-core GEMM, 2-stage double buffer, LDSM A-fragments and
// k-pair-packed B (1 LDS.32 per mma B operand).
// Numerics identical to round-4: a = ah + al, C ~= ah*bh + ah*bl + al*bh,
// fp32 accumulate. CTA tile 128x128x32, 256 threads = 8 warps (2x4),
// warp tile 64x32, mma.sync.aligned.m16n8k16.row.col.f32.bf16.bf16.f32.
//
// SMEM per stage:
//   Ah: 128 rows x SA(=40) ushorts           = 10240 B   (K-major, +8 pad)
//   Al: same                                  = 10240 B
//   Bph: 16 kpairs x 136 uint32 (128 n + pad) =  8704 B   (pair-packed)
//   Bpl: same                                 =  8704 B
// ---------------------------------------------------------------------------
#define SA 40
#define BSTRIDE 136                       // uint32 stride per kpair row
#define AH_OFF  0
#define AL_OFF  10240
#define BH_OFF  20480
#define BL_OFF  29184
#define STAGE_BYTES 37888
#define GEMM_SMEM_BYTES (2 * STAGE_BYTES)   // 75776

__device__ __forceinline__ uint32_t smem_u32(const void* p)
{
    uint32_t a;
    asm("{ .reg .u64 t; cvta.to.shared.u64 t, %1; cvt.u32.u64 %0, t; }" : "=r"(a) : "l"(p));
    return a;
}

__device__ __forceinline__ void bf16_split(float v, unsigned short& h, unsigned short& l)
{
    __nv_bfloat16 bh = __float2bfloat16(v);
    float r = v - __bfloat162float(bh);
    __nv_bfloat16 bl = __float2bfloat16(r);
    h = reinterpret_cast<unsigned short&>(bh);
    l = reinterpret_cast<unsigned short&>(bl);
}

// pack adjacent elements (for A: k-contiguous)
__device__ __forceinline__ void split4_pairs(float4 v, uint2& h, uint2& l)
{
    unsigned short h0,l0,h1,l1,h2,l2,h3,l3;
    bf16_split(v.x,h0,l0); bf16_split(v.y,h1,l1);
    bf16_split(v.z,h2,l2); bf16_split(v.w,h3,l3);
    h.x = (unsigned)h0 | ((unsigned)h1 << 16);
    h.y = (unsigned)h2 | ((unsigned)h3 << 16);
    l.x = (unsigned)l0 | ((unsigned)l1 << 16);
    l.y = (unsigned)l2 | ((unsigned)l3 << 16);
}

// element-wise split (for B k-pair packing)
__device__ __forceinline__ void split4_elems(float4 v, unsigned short h[4], unsigned short l[4])
{
    bf16_split(v.x, h[0], l[0]); bf16_split(v.y, h[1], l[1]);
    bf16_split(v.z, h[2], l[2]); bf16_split(v.w, h[3], l[3]);
}

__device__ __forceinline__ void mma16816(float* c, const unsigned* a, unsigned b0, unsigned b1)
{
    asm volatile(
        "mma.sync.aligned.m16n8k16.row.col.f32.bf16.bf16.f32 "
        "{%0,%1,%2,%3},{%4,%5,%6,%7},{%8,%9},{%0,%1,%2,%3};\n"
        : "+f"(c[0]), "+f"(c[1]), "+f"(c[2]), "+f"(c[3])
        : "r"(a[0]), "r"(a[1]), "r"(a[2]), "r"(a[3]), "r"(b0), "r"(b1));
}

#define LDSM_X4(r, addr) \
    asm volatile("ldmatrix.sync.aligned.m8n8.x4.shared.b16 {%0,%1,%2,%3}, [%4];" \
        : "=r"((r)[0]), "=r"((r)[1]), "=r"((r)[2]), "=r"((r)[3]) : "r"(addr))

__device__ __forceinline__
void gemm_tc_body(const float* __restrict__ A, const float* __restrict__ B,
                  const float* __restrict__ bias, float* __restrict__ C,
                  int N, int K)
{
    extern __shared__ __align__(16) unsigned char dsm[];

    const int tid  = threadIdx.x;
    const int lane = tid & 31;
    const int warp = tid >> 5;
    const int wm   = warp >> 2;      // 0..1
    const int wn   = warp & 3;       // 0..3
    const int grp  = lane >> 2;      // 0..7
    const int tg   = lane & 3;       // 0..3

    const int col0 = blockIdx.x * 128;
    const int row0 = blockIdx.y * 128;

    // A loader: 4 float4 per thread (128 rows x 32 k)
    int aRow[4], aK[4];
#pragma unroll
    for (int i = 0; i < 4; i++) {
        int idx = tid + i * 256;
        aRow[i] = idx >> 3;  aK[i] = (idx & 7) * 4;
    }
    // B loader: 2 (kpair, n4) units per thread; each unit loads rows 2kp, 2kp+1
    int bKp[2], bNc[2];
#pragma unroll
    for (int i = 0; i < 2; i++) {
        int u = tid + i * 256;          // 0..511 -> 16 kpairs x 32 n-chunks
        bKp[i] = u >> 5;  bNc[i] = (u & 31) * 4;
    }

    // ldmatrix per-lane element offset within A buffers
    const int arow_l = lane & 15;
    const int acol_l = (lane & 16) ? 8 : 0;
    const int aoff_l = (wm * 64 + arow_l) * SA + acol_l;   // + mt*16*SA + k0 per frag

    float acc[4][4][4];
#pragma unroll
    for (int mt = 0; mt < 4; mt++)
#pragma unroll
        for (int nt = 0; nt < 4; nt++)
#pragma unroll
            for (int q = 0; q < 4; q++) acc[mt][nt][q] = 0.f;

    float4 pa[4], pb0[2], pb1[2];

    auto load_tile = [&](int k0) {
#pragma unroll
        for (int i = 0; i < 4; i++)
            pa[i] = *(const float4*)(A + (size_t)(row0 + aRow[i]) * K + k0 + aK[i]);
#pragma unroll
        for (int i = 0; i < 2; i++) {
            const float* bp = B + (size_t)(k0 + 2 * bKp[i]) * N + col0 + bNc[i];
            pb0[i] = *(const float4*)bp;
            pb1[i] = *(const float4*)(bp + N);
        }
    };

    auto store_stage = [&](int st) {
        unsigned char* sbp = dsm + st * STAGE_BYTES;
        unsigned short* Ash = (unsigned short*)(sbp + AH_OFF);
        unsigned short* Asl = (unsigned short*)(sbp + AL_OFF);
        uint32_t* Bph = (uint32_t*)(sbp + BH_OFF);
        uint32_t* Bpl = (uint32_t*)(sbp + BL_OFF);
#pragma unroll
        for (int i = 0; i < 4; i++) {
            uint2 h, l;  split4_pairs(pa[i], h, l);
            int ba = aRow[i] * SA + aK[i];
            *(uint2*)&Ash[ba] = h;
            *(uint2*)&Asl[ba] = l;
        }
#pragma unroll
        for (int i = 0; i < 2; i++) {
            unsigned short h0[4], l0[4], h1[4], l1[4];
            split4_elems(pb0[i], h0, l0);
            split4_elems(pb1[i], h1, l1);
            uint4 ph, pl;
            ph.x = (unsigned)h0[0] | ((unsigned)h1[0] << 16);
            ph.y = (unsigned)h0[1] | ((unsigned)h1[1] << 16);
            ph.z = (unsigned)h0[2] | ((unsigned)h1[2] << 16);
            ph.w = (unsigned)h0[3] | ((unsigned)h1[3] << 16);
            pl.x = (unsigned)l0[0] | ((unsigned)l1[0] << 16);
            pl.y = (unsigned)l0[1] | ((unsigned)l1[1] << 16);
            pl.z = (unsigned)l0[2] | ((unsigned)l1[2] << 16);
            pl.w = (unsigned)l0[3] | ((unsigned)l1[3] << 16);
            int bo = bKp[i] * BSTRIDE + bNc[i];
            *(uint4*)&Bph[bo] = ph;
            *(uint4*)&Bpl[bo] = pl;
        }
    };

    auto compute_stage = [&](int st) {
        unsigned char* sbp = dsm + st * STAGE_BYTES;
        const uint32_t ah_base = smem_u32(sbp + AH_OFF);
        const uint32_t al_base = smem_u32(sbp + AL_OFF);
        const uint32_t* Bph = (const uint32_t*)(sbp + BH_OFF);
        const uint32_t* Bpl = (const uint32_t*)(sbp + BL_OFF);
#pragma unroll
        for (int ks = 0; ks < 2; ks++) {
            const int k0 = ks * 16;
            unsigned ah[4][4], al[4][4];
#pragma unroll
            for (int mt = 0; mt < 4; mt++) {
                const uint32_t boff = (uint32_t)(aoff_l + mt * 16 * SA + k0) * 2u;
                LDSM_X4(ah[mt], ah_base + boff);
                LDSM_X4(al[mt], al_base + boff);
            }
            const int kpb = (k0 >> 1) + tg;   // pair row base
#pragma unroll
            for (int nt = 0; nt < 4; nt++) {
                const int n = wn * 32 + nt * 8 + grp;
                unsigned bh0 = Bph[kpb * BSTRIDE + n];
                unsigned bh1 = Bph[(kpb + 4) * BSTRIDE + n];
                unsigned bl0 = Bpl[kpb * BSTRIDE + n];
                unsigned bl1 = Bpl[(kpb + 4) * BSTRIDE + n];
#pragma unroll
                for (int mt = 0; mt < 4; mt++) {
                    mma16816(acc[mt][nt], ah[mt], bh0, bh1);  // hi*hi
                    mma16816(acc[mt][nt], ah[mt], bl0, bl1);  // hi*lo
                    mma16816(acc[mt][nt], al[mt], bh0, bh1);  // lo*hi
                }
            }
        }
    };

    const int NITER = K / 32;

    load_tile(0);
    store_stage(0);
    __syncthreads();

    for (int it = 0; it < NITER; ++it) {
        const int cur = it & 1;
        const bool more = (it + 1 < NITER);
        if (more) load_tile((it + 1) * 32);
        compute_stage(cur);
        if (more) {
            store_stage(cur ^ 1);
            __syncthreads();
        }
    }

    // epilogue: bias + relu, float2 stores
#pragma unroll
    for (int mt = 0; mt < 4; mt++) {
        const int r = row0 + wm * 64 + mt * 16 + grp;
#pragma unroll
        for (int nt = 0; nt < 4; nt++) {
            const int c = col0 + wn * 32 + nt * 8 + 2 * tg;
            const float2 bv = *(const float2*)(bias + c);
            float2 o;
            o.x = fmaxf(acc[mt][nt][0] + bv.x, 0.f);
            o.y = fmaxf(acc[mt][nt][1] + bv.y, 0.f);
            *(float2*)&C[(size_t)r * N + c] = o;
            o.x = fmaxf(acc[mt][nt][2] + bv.x, 0.f);
            o.y = fmaxf(acc[mt][nt][3] + bv.y, 0.f);
            *(float2*)&C[(size_t)(r + 8) * N + c] = o;
        }
    }
}

__global__ __launch_bounds__(256, 1)
void gemm1_kernel(const float* __restrict__ x, const float* __restrict__ W1,
                  const float* __restrict__ b1)
{
    gemm_tc_body(x, W1, b1, g_h1, H1, INF);
}

__global__ __launch_bounds__(256, 1)
void gemm2_kernel(const float* __restrict__ W2, const float* __restrict__ b2)
{
    gemm_tc_body(g_h1, W2, b2, g_h2, H2, H1);
}

// ---------------------------------------------------------------------------
// Gather + dot + BCE + sigmoid (round-8 exact: GSPLIT CTAs per batch row,
// SMEM-staged h). emb rows 4-byte aligned only -> scalar LDG.32.
// ---------------------------------------------------------------------------
__global__ __launch_bounds__(256)
void gather_bce_kernel(const float* __restrict__ emb,
                       const int*   __restrict__ ids,
                       const float* __restrict__ tv,
                       const float* __restrict__ tm,
                       float* __restrict__ probs)
{
    __shared__ float hs[H2];
    __shared__ float warp_part[8];

    if (probs == nullptr) probs = g_scratch;

    const int blk   = blockIdx.x;
    const int b     = blk >> 2;        // GSPLIT == 4
    const int chunk = blk & 3;
    const int tid   = threadIdx.x;
    const int lane  = tid & 31;
    const int w     = tid >> 5;

    ((float4*)hs)[tid] = ((const float4*)(g_h2 + (size_t)b * H2))[tid];
    __syncthreads();

    const int tbase = chunk * TPC;
    float part = 0.f;
    for (int tl = w; tl < TPC; tl += 8) {
        const int t  = tbase + tl;
        const int id = ids[b * TT + t];
        float z = 0.f;
        if (id != 0) {
            const float* er = emb + (size_t)id * EMBED;
            float acc = 0.f;
#pragma unroll
            for (int i = 0; i < 32; i++)
                acc = fmaf(__ldg(er + lane + i * 32), hs[lane + i * 32], acc);
#pragma unroll
            for (int o = 16; o; o >>= 1)
                acc += __shfl_xor_sync(0xffffffffu, acc, o);
            z = acc + __ldg(er + 1024);
        }
        if (lane == 0) {
            const float y = tv[b * TT + t];
            const float m = tm[b * TT + t];
            const float bce = fmaxf(z, 0.f) - z * y + log1pf(expf(-fabsf(z)));
            part += m * bce;
            probs[b * TT + t] = 1.f / (1.f + expf(-z));
        }
    }
    if (lane == 0) warp_part[w] = part;
    __syncthreads();
    if (tid == 0) {
        float s = 0.f;
#pragma unroll
        for (int i = 0; i < 8; i++) s += warp_part[i];
        g_partials[blk] = s;
    }
}

// Deterministic final reduction: fixed-order tree over BB*GSPLIT partials.
__global__ __launch_bounds__(256)
void finalize_loss(float* __restrict__ out)
{
    __shared__ float s[256];
    float acc = 0.f;
    for (int i = threadIdx.x; i < BB * GSPLIT; i += 256) acc += g_partials[i];
    s[threadIdx.x] = acc;
    __syncthreads();
    for (int o = 128; o; o >>= 1) {
        if (threadIdx.x < o) s[threadIdx.x] += s[threadIdx.x + o];
        __syncthreads();
    }
    if (threadIdx.x == 0) out[0] = s[0] / (float)((size_t)BB * TT);
}

// ---------------------------------------------------------------------------
extern "C" void kernel_launch(void* const* d_in, const int* in_sizes, int n_in,
                              void* d_out, int out_size)
{
    const float* x   = (const float*)d_in[0];
    const float* W1  = (const float*)d_in[1];
    const float* b1  = (const float*)d_in[2];
    const float* W2  = (const float*)d_in[3];
    const float* b2  = (const float*)d_in[4];
    const float* emb = (const float*)d_in[5];
    const int*   ids = (const int*)  d_in[6];
    const float* tv  = (const float*)d_in[7];
    const float* tm  = (const float*)d_in[8];
    float* out = (float*)d_out;

    cudaFuncSetAttribute(gemm1_kernel, cudaFuncAttributeMaxDynamicSharedMemorySize, GEMM_SMEM_BYTES);
    cudaFuncSetAttribute(gemm2_kernel, cudaFuncAttributeMaxDynamicSharedMemorySize, GEMM_SMEM_BYTES);

    // GEMM1: [2048,1024] @ [1024,2048] -> g_h1
    {
        dim3 grid(H1 / 128, BB / 128);
        gemm1_kernel<<<grid, 256, GEMM_SMEM_BYTES>>>(x, W1, b1);
    }
    // GEMM2: [2048,2048] @ [2048,1024] -> g_h2
    {
        dim3 grid(H2 / 128, BB / 128);
        gemm2_kernel<<<grid, 256, GEMM_SMEM_BYTES>>>(W2, b2);
    }

    const int nBT = BB * TT;
    float* probs    = nullptr;   // nullptr -> scratch inside kernel
    float* loss_dst = nullptr;
    if (out_size >= nBT + 1)      { loss_dst = out; probs = out + 1; }
    else if (out_size == nBT)     { probs = out; }
    else                          { loss_dst = out; }

    gather_bce_kernel<<<BB * GSPLIT, 256>>>(emb, ids, tv, tm, probs);

    if (loss_dst != nullptr) {
        finalize_loss<<<1, 256>>>(loss_dst);
    }
}

// round 12
// speedup vs baseline: 1.1758x; 1.0344x over previous
#include <cuda_runtime.h>
#include <cuda_bf16.h>
#include <cstdint>

// Problem dims
#define BB    2048
#define TT    200
#define INF   1024
#define H1    2048
#define H2    1024
#define EMBED 1025   // H2 + 1 bias column
#define NROWS 100001 // VOCAB + 1
#define PROW  513    // uint32 per packed bf16 row (1024 data + bias + pad)

#define GSPLIT 4                 // CTAs per batch row in gather
#define TPC    (TT / GSPLIT)     // 50 targets per CTA

// Scratch (device globals; no allocation allowed)
__device__ float    g_h1[(size_t)BB * H1];        // 16 MB
__device__ float    g_h2[(size_t)BB * H2];        // 8 MB
__device__ float    g_scratch[(size_t)BB * TT];   // probs scratch (loss-only layout)
__device__ float    g_partials[BB * GSPLIT];      // per-CTA partial sums
__device__ uint32_t g_embp[(size_t)NROWS * PROW]; // 205 MB packed bf16 emb

// ---------------------------------------------------------------------------
// Split-bf16 tensor-core GEMM (round-11 exact, passing): 2-stage double
// buffer, LDSM A-fragments, k-pair-packed B. a=ah+al, C ~= ah*bh+ah*bl+al*bh.
// ---------------------------------------------------------------------------
#define SA 40
#define BSTRIDE 136
#define AH_OFF  0
#define AL_OFF  10240
#define BH_OFF  20480
#define BL_OFF  29184
#define STAGE_BYTES 37888
#define GEMM_SMEM_BYTES (2 * STAGE_BYTES)   // 75776

__device__ __forceinline__ uint32_t smem_u32(const void* p)
{
    uint32_t a;
    asm("{ .reg .u64 t; cvta.to.shared.u64 t, %1; cvt.u32.u64 %0, t; }" : "=r"(a) : "l"(p));
    return a;
}

__device__ __forceinline__ void bf16_split(float v, unsigned short& h, unsigned short& l)
{
    __nv_bfloat16 bh = __float2bfloat16(v);
    float r = v - __bfloat162float(bh);
    __nv_bfloat16 bl = __float2bfloat16(r);
    h = reinterpret_cast<unsigned short&>(bh);
    l = reinterpret_cast<unsigned short&>(bl);
}

__device__ __forceinline__ void split4_pairs(float4 v, uint2& h, uint2& l)
{
    unsigned short h0,l0,h1,l1,h2,l2,h3,l3;
    bf16_split(v.x,h0,l0); bf16_split(v.y,h1,l1);
    bf16_split(v.z,h2,l2); bf16_split(v.w,h3,l3);
    h.x = (unsigned)h0 | ((unsigned)h1 << 16);
    h.y = (unsigned)h2 | ((unsigned)h3 << 16);
    l.x = (unsigned)l0 | ((unsigned)l1 << 16);
    l.y = (unsigned)l2 | ((unsigned)l3 << 16);
}

__device__ __forceinline__ void split4_elems(float4 v, unsigned short h[4], unsigned short l[4])
{
    bf16_split(v.x, h[0], l[0]); bf16_split(v.y, h[1], l[1]);
    bf16_split(v.z, h[2], l[2]); bf16_split(v.w, h[3], l[3]);
}

__device__ __forceinline__ void mma16816(float* c, const unsigned* a, unsigned b0, unsigned b1)
{
    asm volatile(
        "mma.sync.aligned.m16n8k16.row.col.f32.bf16.bf16.f32 "
        "{%0,%1,%2,%3},{%4,%5,%6,%7},{%8,%9},{%0,%1,%2,%3};\n"
        : "+f"(c[0]), "+f"(c[1]), "+f"(c[2]), "+f"(c[3])
        : "r"(a[0]), "r"(a[1]), "r"(a[2]), "r"(a[3]), "r"(b0), "r"(b1));
}

#define LDSM_X4(r, addr) \
    asm volatile("ldmatrix.sync.aligned.m8n8.x4.shared.b16 {%0,%1,%2,%3}, [%4];" \
        : "=r"((r)[0]), "=r"((r)[1]), "=r"((r)[2]), "=r"((r)[3]) : "r"(addr))

__device__ __forceinline__
void gemm_tc_body(const float* __restrict__ A, const float* __restrict__ B,
                  const float* __restrict__ bias, float* __restrict__ C,
                  int N, int K)
{
    extern __shared__ __align__(16) unsigned char dsm[];

    const int tid  = threadIdx.x;
    const int lane = tid & 31;
    const int warp = tid >> 5;
    const int wm   = warp >> 2;
    const int wn   = warp & 3;
    const int grp  = lane >> 2;
    const int tg   = lane & 3;

    const int col0 = blockIdx.x * 128;
    const int row0 = blockIdx.y * 128;

    int aRow[4], aK[4];
#pragma unroll
    for (int i = 0; i < 4; i++) {
        int idx = tid + i * 256;
        aRow[i] = idx >> 3;  aK[i] = (idx & 7) * 4;
    }
    int bKp[2], bNc[2];
#pragma unroll
    for (int i = 0; i < 2; i++) {
        int u = tid + i * 256;
        bKp[i] = u >> 5;  bNc[i] = (u & 31) * 4;
    }

    const int arow_l = lane & 15;
    const int acol_l = (lane & 16) ? 8 : 0;
    const int aoff_l = (wm * 64 + arow_l) * SA + acol_l;

    float acc[4][4][4];
#pragma unroll
    for (int mt = 0; mt < 4; mt++)
#pragma unroll
        for (int nt = 0; nt < 4; nt++)
#pragma unroll
            for (int q = 0; q < 4; q++) acc[mt][nt][q] = 0.f;

    float4 pa[4], pb0[2], pb1[2];

    auto load_tile = [&](int k0) {
#pragma unroll
        for (int i = 0; i < 4; i++)
            pa[i] = *(const float4*)(A + (size_t)(row0 + aRow[i]) * K + k0 + aK[i]);
#pragma unroll
        for (int i = 0; i < 2; i++) {
            const float* bp = B + (size_t)(k0 + 2 * bKp[i]) * N + col0 + bNc[i];
            pb0[i] = *(const float4*)bp;
            pb1[i] = *(const float4*)(bp + N);
        }
    };

    auto store_stage = [&](int st) {
        unsigned char* sbp = dsm + st * STAGE_BYTES;
        unsigned short* Ash = (unsigned short*)(sbp + AH_OFF);
        unsigned short* Asl = (unsigned short*)(sbp + AL_OFF);
        uint32_t* Bph = (uint32_t*)(sbp + BH_OFF);
        uint32_t* Bpl = (uint32_t*)(sbp + BL_OFF);
#pragma unroll
        for (int i = 0; i < 4; i++) {
            uint2 h, l;  split4_pairs(pa[i], h, l);
            int ba = aRow[i] * SA + aK[i];
            *(uint2*)&Ash[ba] = h;
            *(uint2*)&Asl[ba] = l;
        }
#pragma unroll
        for (int i = 0; i < 2; i++) {
            unsigned short h0[4], l0[4], h1[4], l1[4];
            split4_elems(pb0[i], h0, l0);
            split4_elems(pb1[i], h1, l1);
            uint4 ph, pl;
            ph.x = (unsigned)h0[0] | ((unsigned)h1[0] << 16);
            ph.y = (unsigned)h0[1] | ((unsigned)h1[1] << 16);
            ph.z = (unsigned)h0[2] | ((unsigned)h1[2] << 16);
            ph.w = (unsigned)h0[3] | ((unsigned)h1[3] << 16);
            pl.x = (unsigned)l0[0] | ((unsigned)l1[0] << 16);
            pl.y = (unsigned)l0[1] | ((unsigned)l1[1] << 16);
            pl.z = (unsigned)l0[2] | ((unsigned)l1[2] << 16);
            pl.w = (unsigned)l0[3] | ((unsigned)l1[3] << 16);
            int bo = bKp[i] * BSTRIDE + bNc[i];
            *(uint4*)&Bph[bo] = ph;
            *(uint4*)&Bpl[bo] = pl;
        }
    };

    auto compute_stage = [&](int st) {
        unsigned char* sbp = dsm + st * STAGE_BYTES;
        const uint32_t ah_base = smem_u32(sbp + AH_OFF);
        const uint32_t al_base = smem_u32(sbp + AL_OFF);
        const uint32_t* Bph = (const uint32_t*)(sbp + BH_OFF);
        const uint32_t* Bpl = (const uint32_t*)(sbp + BL_OFF);
#pragma unroll
        for (int ks = 0; ks < 2; ks++) {
            const int k0 = ks * 16;
            unsigned ah[4][4], al[4][4];
#pragma unroll
            for (int mt = 0; mt < 4; mt++) {
                const uint32_t boff = (uint32_t)(aoff_l + mt * 16 * SA + k0) * 2u;
                LDSM_X4(ah[mt], ah_base + boff);
                LDSM_X4(al[mt], al_base + boff);
            }
            const int kpb = (k0 >> 1) + tg;
#pragma unroll
            for (int nt = 0; nt < 4; nt++) {
                const int n = wn * 32 + nt * 8 + grp;
                unsigned bh0 = Bph[kpb * BSTRIDE + n];
                unsigned bh1 = Bph[(kpb + 4) * BSTRIDE + n];
                unsigned bl0 = Bpl[kpb * BSTRIDE + n];
                unsigned bl1 = Bpl[(kpb + 4) * BSTRIDE + n];
#pragma unroll
                for (int mt = 0; mt < 4; mt++) {
                    mma16816(acc[mt][nt], ah[mt], bh0, bh1);
                    mma16816(acc[mt][nt], ah[mt], bl0, bl1);
                    mma16816(acc[mt][nt], al[mt], bh0, bh1);
                }
            }
        }
    };

    const int NITER = K / 32;

    load_tile(0);
    store_stage(0);
    __syncthreads();

    for (int it = 0; it < NITER; ++it) {
        const int cur = it & 1;
        const bool more = (it + 1 < NITER);
        if (more) load_tile((it + 1) * 32);
        compute_stage(cur);
        if (more) {
            store_stage(cur ^ 1);
            __syncthreads();
        }
    }

#pragma unroll
    for (int mt = 0; mt < 4; mt++) {
        const int r = row0 + wm * 64 + mt * 16 + grp;
#pragma unroll
        for (int nt = 0; nt < 4; nt++) {
            const int c = col0 + wn * 32 + nt * 8 + 2 * tg;
            const float2 bv = *(const float2*)(bias + c);
            float2 o;
            o.x = fmaxf(acc[mt][nt][0] + bv.x, 0.f);
            o.y = fmaxf(acc[mt][nt][1] + bv.y, 0.f);
            *(float2*)&C[(size_t)r * N + c] = o;
            o.x = fmaxf(acc[mt][nt][2] + bv.x, 0.f);
            o.y = fmaxf(acc[mt][nt][3] + bv.y, 0.f);
            *(float2*)&C[(size_t)(r + 8) * N + c] = o;
        }
    }
}

__global__ __launch_bounds__(256, 1)
void gemm1_kernel(const float* __restrict__ x, const float* __restrict__ W1,
                  const float* __restrict__ b1)
{
    gemm_tc_body(x, W1, b1, g_h1, H1, INF);
}

__global__ __launch_bounds__(256, 1)
void gemm2_kernel(const float* __restrict__ W2, const float* __restrict__ b2)
{
    gemm_tc_body(g_h1, W2, b2, g_h2, H2, H1);
}

// ---------------------------------------------------------------------------
// Pack emb (fp32, 1025-stride misaligned rows) -> bf16x2 rows of 513 uint32.
// One warp per row; fully coalesced reads/writes.
// ---------------------------------------------------------------------------
__global__ __launch_bounds__(256)
void pack_emb_kernel(const float* __restrict__ emb)
{
    const int row  = blockIdx.x * 8 + (threadIdx.x >> 5);
    if (row >= NROWS) return;
    const int lane = threadIdx.x & 31;
    const float* src = emb + (size_t)row * EMBED;
    uint32_t* dst = g_embp + (size_t)row * PROW;
#pragma unroll
    for (int i = 0; i < 16; i++) {
        const int j = lane + i * 32;            // uint index 0..511
        float f0 = __ldg(src + 2 * j);
        float f1 = __ldg(src + 2 * j + 1);
        __nv_bfloat16 b0 = __float2bfloat16(f0);
        __nv_bfloat16 b1 = __float2bfloat16(f1);
        dst[j] = (uint32_t)reinterpret_cast<unsigned short&>(b0)
               | ((uint32_t)reinterpret_cast<unsigned short&>(b1) << 16);
    }
    if (lane == 0) {
        __nv_bfloat16 bb = __float2bfloat16(__ldg(src + 1024));
        dst[512] = (uint32_t)reinterpret_cast<unsigned short&>(bb);
    }
}

// ---------------------------------------------------------------------------
// Gather + dot + BCE + sigmoid on packed bf16 emb.
// GSPLIT CTAs per batch row; h2 staged in SMEM (fp32).
// bf16 -> fp32 unpack is an exact shift; accumulate in fp32.
// ---------------------------------------------------------------------------
__global__ __launch_bounds__(256)
void gather_bce_kernel(const int*   __restrict__ ids,
                       const float* __restrict__ tv,
                       const float* __restrict__ tm,
                       float* __restrict__ probs)
{
    __shared__ float hs[H2];
    __shared__ float warp_part[8];

    if (probs == nullptr) probs = g_scratch;

    const int blk   = blockIdx.x;
    const int b     = blk >> 2;        // GSPLIT == 4
    const int chunk = blk & 3;
    const int tid   = threadIdx.x;
    const int lane  = tid & 31;
    const int w     = tid >> 5;

    ((float4*)hs)[tid] = ((const float4*)(g_h2 + (size_t)b * H2))[tid];
    __syncthreads();

    const int tbase = chunk * TPC;
    float part = 0.f;
    for (int tl = w; tl < TPC; tl += 8) {
        const int t  = tbase + tl;
        const int id = ids[b * TT + t];
        float z = 0.f;
        if (id != 0) {
            const uint32_t* er = g_embp + (size_t)id * PROW;
            float acc = 0.f;
#pragma unroll
            for (int i = 0; i < 16; i++) {
                const int j = lane + i * 32;
                const uint32_t u = __ldg(er + j);
                const float2 hv = *(const float2*)&hs[2 * j];
                acc = fmaf(__uint_as_float(u << 16),          hv.x, acc);
                acc = fmaf(__uint_as_float(u & 0xFFFF0000u),  hv.y, acc);
            }
#pragma unroll
            for (int o = 16; o; o >>= 1)
                acc += __shfl_xor_sync(0xffffffffu, acc, o);
            z = acc + __uint_as_float(__ldg(er + 512) << 16);   // bias column
        }
        if (lane == 0) {
            const float y = tv[b * TT + t];
            const float m = tm[b * TT + t];
            const float bce = fmaxf(z, 0.f) - z * y + log1pf(expf(-fabsf(z)));
            part += m * bce;
            probs[b * TT + t] = 1.f / (1.f + expf(-z));
        }
    }
    if (lane == 0) warp_part[w] = part;
    __syncthreads();
    if (tid == 0) {
        float s = 0.f;
#pragma unroll
        for (int i = 0; i < 8; i++) s += warp_part[i];
        g_partials[blk] = s;
    }
}

// Deterministic final reduction.
__global__ __launch_bounds__(256)
void finalize_loss(float* __restrict__ out)
{
    __shared__ float s[256];
    float acc = 0.f;
    for (int i = threadIdx.x; i < BB * GSPLIT; i += 256) acc += g_partials[i];
    s[threadIdx.x] = acc;
    __syncthreads();
    for (int o = 128; o; o >>= 1) {
        if (threadIdx.x < o) s[threadIdx.x] += s[threadIdx.x + o];
        __syncthreads();
    }
    if (threadIdx.x == 0) out[0] = s[0] / (float)((size_t)BB * TT);
}

// ---------------------------------------------------------------------------
extern "C" void kernel_launch(void* const* d_in, const int* in_sizes, int n_in,
                              void* d_out, int out_size)
{
    const float* x   = (const float*)d_in[0];
    const float* W1  = (const float*)d_in[1];
    const float* b1  = (const float*)d_in[2];
    const float* W2  = (const float*)d_in[3];
    const float* b2  = (const float*)d_in[4];
    const float* emb = (const float*)d_in[5];
    const int*   ids = (const int*)  d_in[6];
    const float* tv  = (const float*)d_in[7];
    const float* tm  = (const float*)d_in[8];
    float* out = (float*)d_out;

    cudaFuncSetAttribute(gemm1_kernel, cudaFuncAttributeMaxDynamicSharedMemorySize, GEMM_SMEM_BYTES);
    cudaFuncSetAttribute(gemm2_kernel, cudaFuncAttributeMaxDynamicSharedMemorySize, GEMM_SMEM_BYTES);

    const int packGrid = (NROWS + 7) / 8;

    // Try to fork emb packing onto a side stream (overlaps with both GEMMs).
    // Falls back to serial on the main stream if stream/event setup fails.
    cudaStream_t s2;
    cudaEvent_t e0, e1;
    bool forked = false;
    if (cudaStreamCreateWithFlags(&s2, cudaStreamNonBlocking) == cudaSuccess) {
        if (cudaEventCreateWithFlags(&e0, cudaEventDisableTiming) == cudaSuccess &&
            cudaEventCreateWithFlags(&e1, cudaEventDisableTiming) == cudaSuccess) {
            if (cudaEventRecord(e0, 0) == cudaSuccess &&
                cudaStreamWaitEvent(s2, e0, 0) == cudaSuccess) {
                pack_emb_kernel<<<packGrid, 256, 0, s2>>>(emb);
                if (cudaEventRecord(e1, s2) == cudaSuccess)
                    forked = true;
            }
        }
    }
    if (!forked)
        pack_emb_kernel<<<packGrid, 256>>>(emb);

    // GEMM1: [2048,1024] @ [1024,2048] -> g_h1
    {
        dim3 grid(H1 / 128, BB / 128);
        gemm1_kernel<<<grid, 256, GEMM_SMEM_BYTES>>>(x, W1, b1);
    }
    // GEMM2: [2048,2048] @ [2048,1024] -> g_h2
    {
        dim3 grid(H2 / 128, BB / 128);
        gemm2_kernel<<<grid, 256, GEMM_SMEM_BYTES>>>(W2, b2);
    }

    if (forked)
        cudaStreamWaitEvent(0, e1, 0);   // join: packed emb ready before gather

    const int nBT = BB * TT;
    float* probs    = nullptr;   // nullptr -> scratch inside kernel
    float* loss_dst = nullptr;
    if (out_size >= nBT + 1)      { loss_dst = out; probs = out + 1; }
    else if (out_size == nBT)     { probs = out; }
    else                          { loss_dst = out; }

    gather_bce_kernel<<<BB * GSPLIT, 256>>>(ids, tv, tm, probs);

    if (loss_dst != nullptr) {
        finalize_loss<<<1, 256>>>(loss_dst);
    }
}